// round 7
// baseline (speedup 1.0000x reference)
#include <cuda_runtime.h>
#include <cuda_bf16.h>
#include <math.h>
#include <stdint.h>

// Problem constants
#define B     2
#define S     4096
#define E     1024
#define H     16
#define D     64
#define WIN   256
#define M_ROWS (B * S)        // 8192

// Scratch buffers
__device__ float g_q[B * H * S * D];    // [b,h,s,d]
__device__ float g_k[B * H * S * D];
__device__ float g_v[B * H * S * D];
__device__ float g_ctx[B * S * E];      // [b,s,e]

__device__ __forceinline__ uint32_t f2tf32(float x) {
    uint32_t r;
    asm("cvt.rna.tf32.f32 %0, %1;" : "=r"(r) : "f"(x));
    return r;
}

__device__ __forceinline__ void mma_tf32(float d[4], const uint32_t a[4], const uint32_t b[2]) {
    asm volatile(
        "mma.sync.aligned.m16n8k8.row.col.f32.tf32.tf32.f32 "
        "{%0,%1,%2,%3}, {%4,%5,%6,%7}, {%8,%9}, {%0,%1,%2,%3};"
        : "+f"(d[0]), "+f"(d[1]), "+f"(d[2]), "+f"(d[3])
        : "r"(a[0]), "r"(a[1]), "r"(a[2]), "r"(a[3]), "r"(b[0]), "r"(b[1]));
}

// ---------------------------------------------------------------------------
// tf32 GEMM, 4 warps, 64x64 warp tiles (2x LDS reuse vs 64x32).
// Block 128x128x32, 128 threads. C = A @ Wt^T + bias.
// mode 0: row-major out; mode 1: [b,h,s,d] scatter + head-rope*scale; mode 2: scatter.
// ---------------------------------------------------------------------------
#define BM 128
#define BN 128
#define BK 32
#define SSTR (BK + 4)   // 36

__global__ void __launch_bounds__(128)
tf32_gemm(const float* __restrict__ A, const float* __restrict__ Wt,
          const float* __restrict__ bias, float* __restrict__ C,
          int M, int N, int K, int mode, float scale)
{
    __shared__ uint32_t As[BM][SSTR];
    __shared__ uint32_t Bs[BN][SSTR];

    const int tid  = threadIdx.x;
    const int warp = tid >> 5;
    const int lane = tid & 31;
    const int g    = lane >> 2;
    const int tig  = lane & 3;
    const int wm   = warp & 1;      // 2 m-warps, 64 rows each
    const int wn   = warp >> 1;     // 2 n-warps, 64 cols each

    const int m0 = blockIdx.y * BM;
    const int n0 = blockIdx.x * BN;

    float acc[4][8][4];
    #pragma unroll
    for (int mi = 0; mi < 4; mi++)
        #pragma unroll
        for (int ni = 0; ni < 8; ni++)
            #pragma unroll
            for (int r = 0; r < 4; r++) acc[mi][ni][r] = 0.f;

    const float* Arow = A  + (size_t)(m0 + tid) * K;
    const float* Brow = Wt + (size_t)(n0 + tid) * K;

    for (int k0 = 0; k0 < K; k0 += BK) {
        __syncthreads();
        #pragma unroll
        for (int j = 0; j < 8; j++) {
            float4 a4 = *(const float4*)(Arow + k0 + 4 * j);
            float4 b4 = *(const float4*)(Brow + k0 + 4 * j);
            *(uint4*)&As[tid][4 * j] =
                make_uint4(f2tf32(a4.x), f2tf32(a4.y), f2tf32(a4.z), f2tf32(a4.w));
            *(uint4*)&Bs[tid][4 * j] =
                make_uint4(f2tf32(b4.x), f2tf32(b4.y), f2tf32(b4.z), f2tf32(b4.w));
        }
        __syncthreads();

        #pragma unroll
        for (int ks = 0; ks < 4; ks++) {
            const int kb = ks * 8;
            uint32_t af[4][4];
            #pragma unroll
            for (int mi = 0; mi < 4; mi++) {
                int rm = wm * 64 + mi * 16;
                af[mi][0] = As[rm + g][kb + tig];
                af[mi][1] = As[rm + g + 8][kb + tig];
                af[mi][2] = As[rm + g][kb + tig + 4];
                af[mi][3] = As[rm + g + 8][kb + tig + 4];
            }
            uint32_t bf[8][2];
            #pragma unroll
            for (int ni = 0; ni < 8; ni++) {
                int cb = wn * 64 + ni * 8;
                bf[ni][0] = Bs[cb + g][kb + tig];
                bf[ni][1] = Bs[cb + g][kb + tig + 4];
            }
            #pragma unroll
            for (int mi = 0; mi < 4; mi++)
                #pragma unroll
                for (int ni = 0; ni < 8; ni++)
                    mma_tf32(acc[mi][ni], af[mi], bf[ni]);
        }
    }

    const float Lc = 13.287712379549449f / 32.0f;  // log2(10000)/32
    #pragma unroll
    for (int mi = 0; mi < 4; mi++) {
        #pragma unroll
        for (int ni = 0; ni < 8; ni++) {
            int c0 = n0 + wn * 64 + ni * 8 + 2 * tig;
            float bias0 = bias[c0];
            float bias1 = bias[c0 + 1];
            #pragma unroll
            for (int rr = 0; rr < 2; rr++) {
                int n = m0 + wm * 64 + mi * 16 + g + rr * 8;
                float x0 = acc[mi][ni][2 * rr + 0] + bias0;
                float x1 = acc[mi][ni][2 * rr + 1] + bias1;
                float o0, o1;
                if (mode == 1) {
                    int hh = c0 >> 6;
                    int mm0 = c0 & 31;
                    int mm1 = (c0 + 1) & 31;
                    float f0 = exp2f(-(float)mm0 * Lc);
                    float f1 = exp2f(-(float)mm1 * Lc);
                    float s0, cs0, s1, cs1;
                    sincosf((float)hh * f0, &s0, &cs0);
                    sincosf((float)hh * f1, &s1, &cs1);
                    o0 = (x0 * cs0 - x1 * s0) * scale;
                    o1 = (x1 * cs1 + x0 * s1) * scale;
                } else {
                    o0 = x0;
                    o1 = x1;
                }
                if (mode == 0) {
                    *(float2*)&C[(size_t)n * N + c0] = make_float2(o0, o1);
                } else {
                    int bb = n >> 12;
                    int sr = n & 4095;
                    int hh = c0 >> 6;
                    int dd = c0 & 63;
                    float* dst = C + ((size_t)((bb << 4) + hh) * 4096 + sr) * 64 + dd;
                    *(float2*)dst = make_float2(o0, o1);
                }
            }
        }
    }
}

// ---------------------------------------------------------------------------
// Flash attention, tf32 MMA. 128-query blocks, 4 warps (32 q each, mi=0,1).
// 20 key tiles of 32 covering [q0-256, q0+383]. V row-major (stride 72).
// smem u32: Ks [32][68] @0, Vs [32][72] @2176, Ps [128][36] @4480 -> 9088.
// Q staged at base (128*68=8704 <= 9088) before K/V use.
// ---------------------------------------------------------------------------
#define AT_VS 2176
#define AT_PS 4480
#define AT_SM 9088

__global__ void __launch_bounds__(128)
attn_mma()
{
    __shared__ uint32_t sm[AT_SM];

    const int t    = threadIdx.x;
    const int lane = t & 31;
    const int warp = t >> 5;
    const int g    = lane >> 2;
    const int tig  = lane & 3;
    const int qb   = blockIdx.x;
    const int bh   = blockIdx.y;
    const int q0   = qb * 128;

    const float* qg = g_q + (size_t)bh * S * D;
    const float* kg = g_k + (size_t)bh * S * D;
    const float* vg = g_v + (size_t)bh * S * D;

    // ---- stage Q (tf32): 128 rows, 1 row/thread ----
    {
        uint32_t* Qs = sm;   // [128][68]
        const float4* src = (const float4*)(qg + (size_t)(q0 + t) * D);
        #pragma unroll
        for (int i = 0; i < 16; i++) {
            float4 v4 = src[i];
            *(uint4*)&Qs[t * 68 + 4 * i] =
                make_uint4(f2tf32(v4.x), f2tf32(v4.y), f2tf32(v4.z), f2tf32(v4.w));
        }
    }
    __syncthreads();
    uint32_t qf[2][8][4];
    {
        const uint32_t* Qs = sm;
        #pragma unroll
        for (int mi = 0; mi < 2; mi++) {
            int r0 = (warp * 32 + mi * 16 + g) * 68;
            int r1 = r0 + 8 * 68;
            #pragma unroll
            for (int ks = 0; ks < 8; ks++) {
                int c = ks * 8 + tig;
                qf[mi][ks][0] = Qs[r0 + c];
                qf[mi][ks][1] = Qs[r1 + c];
                qf[mi][ks][2] = Qs[r0 + c + 4];
                qf[mi][ks][3] = Qs[r1 + c + 4];
            }
        }
    }
    __syncthreads();

    uint32_t* Ks = sm;            // [32][68]
    uint32_t* Vs = sm + AT_VS;    // [32][72] row-major
    uint32_t* Ps = sm + AT_PS;    // [128][36]

    float ctx[2][8][4];
    #pragma unroll
    for (int mi = 0; mi < 2; mi++)
        #pragma unroll
        for (int nf = 0; nf < 8; nf++)
            #pragma unroll
            for (int c = 0; c < 4; c++) ctx[mi][nf][c] = 0.f;
    float mrow[2][2], lrow[2][2];
    #pragma unroll
    for (int mi = 0; mi < 2; mi++) {
        mrow[mi][0] = mrow[mi][1] = -3.0e38f;
        lrow[mi][0] = lrow[mi][1] = 0.f;
    }

    const int qpw = q0 + warp * 32 + g;   // + mi*16 (+8 for row1)

    int kbase = q0 - 256;
    for (int kt = 0; kt < 20; kt++, kbase += 32) {
        // ---- load K tile [32][68] + V tile [32][72] ----
        {
            int lr = t >> 2;              // key row 0..31
            int lc = (t & 3) * 16;        // d col
            int kr = kbase + lr;
            bool ok = (kr >= 0) && (kr < S);
            const float4* kp = (const float4*)(kg + (size_t)(ok ? kr : 0) * D + lc);
            const float4* vp = (const float4*)(vg + (size_t)(ok ? kr : 0) * D + lc);
            float4 z4 = make_float4(0.f, 0.f, 0.f, 0.f);
            #pragma unroll
            for (int i = 0; i < 4; i++) {
                float4 kv = ok ? kp[i] : z4;
                float4 vv = ok ? vp[i] : z4;
                *(uint4*)&Ks[lr * 68 + lc + 4 * i] =
                    make_uint4(f2tf32(kv.x), f2tf32(kv.y), f2tf32(kv.z), f2tf32(kv.w));
                *(uint4*)&Vs[lr * 72 + lc + 4 * i] =
                    make_uint4(f2tf32(vv.x), f2tf32(vv.y), f2tf32(vv.z), f2tf32(vv.w));
            }
        }
        __syncthreads();

        // ---- QK^T: per warp 32q x 32k ; bf shared across mi ----
        float sc[2][4][4];
        #pragma unroll
        for (int mi = 0; mi < 2; mi++)
            #pragma unroll
            for (int nf = 0; nf < 4; nf++)
                #pragma unroll
                for (int c = 0; c < 4; c++) sc[mi][nf][c] = 0.f;

        #pragma unroll
        for (int ks = 0; ks < 8; ks++) {
            uint32_t bf[4][2];
            #pragma unroll
            for (int nf = 0; nf < 4; nf++) {
                int r = (nf * 8 + g) * 68 + ks * 8 + tig;
                bf[nf][0] = Ks[r];
                bf[nf][1] = Ks[r + 4];
            }
            #pragma unroll
            for (int mi = 0; mi < 2; mi++)
                #pragma unroll
                for (int nf = 0; nf < 4; nf++)
                    mma_tf32(sc[mi][nf], qf[mi][ks], bf[nf]);
        }

        // ---- mask + online softmax + P store (per mi) ----
        #pragma unroll
        for (int mi = 0; mi < 2; mi++) {
            const int qp0 = qpw + mi * 16;
            float mx0 = -3.0e38f, mx1 = -3.0e38f;
            #pragma unroll
            for (int nf = 0; nf < 4; nf++) {
                int kp0 = kbase + nf * 8 + 2 * tig;
                #pragma unroll
                for (int c = 0; c < 4; c++) {
                    int kpos = kp0 + (c & 1);
                    int qpos = qp0 + (c >> 1) * 8;
                    int dlt  = kpos - qpos;
                    bool valid = (dlt >= -WIN) && (dlt <= WIN) && (kpos >= 0) && (kpos < S);
                    if (!valid) sc[mi][nf][c] = -3.0e38f;
                }
                mx0 = fmaxf(mx0, fmaxf(sc[mi][nf][0], sc[mi][nf][1]));
                mx1 = fmaxf(mx1, fmaxf(sc[mi][nf][2], sc[mi][nf][3]));
            }
            mx0 = fmaxf(mx0, __shfl_xor_sync(0xffffffffu, mx0, 1));
            mx0 = fmaxf(mx0, __shfl_xor_sync(0xffffffffu, mx0, 2));
            mx1 = fmaxf(mx1, __shfl_xor_sync(0xffffffffu, mx1, 1));
            mx1 = fmaxf(mx1, __shfl_xor_sync(0xffffffffu, mx1, 2));

            float mn0 = fmaxf(fmaxf(mrow[mi][0], mx0), -1.0e30f);
            float mn1 = fmaxf(fmaxf(mrow[mi][1], mx1), -1.0e30f);
            float sc0 = __expf(mrow[mi][0] - mn0);
            float sc1 = __expf(mrow[mi][1] - mn1);
            mrow[mi][0] = mn0; mrow[mi][1] = mn1;

            float rs0 = 0.f, rs1 = 0.f;
            const int prb = (warp * 32 + mi * 16 + g) * 36;
            #pragma unroll
            for (int nf = 0; nf < 4; nf++) {
                float p0 = __expf(sc[mi][nf][0] - mn0);
                float p1 = __expf(sc[mi][nf][1] - mn0);
                float p2 = __expf(sc[mi][nf][2] - mn1);
                float p3 = __expf(sc[mi][nf][3] - mn1);
                rs0 += p0 + p1;
                rs1 += p2 + p3;
                int cofs = nf * 8 + 2 * tig;
                *(uint2*)&Ps[prb + cofs]          = make_uint2(f2tf32(p0), f2tf32(p1));
                *(uint2*)&Ps[prb + 8 * 36 + cofs] = make_uint2(f2tf32(p2), f2tf32(p3));
            }
            rs0 += __shfl_xor_sync(0xffffffffu, rs0, 1);
            rs0 += __shfl_xor_sync(0xffffffffu, rs0, 2);
            rs1 += __shfl_xor_sync(0xffffffffu, rs1, 1);
            rs1 += __shfl_xor_sync(0xffffffffu, rs1, 2);
            lrow[mi][0] = lrow[mi][0] * sc0 + rs0;
            lrow[mi][1] = lrow[mi][1] * sc1 + rs1;

            #pragma unroll
            for (int nf = 0; nf < 8; nf++) {
                ctx[mi][nf][0] *= sc0; ctx[mi][nf][1] *= sc0;
                ctx[mi][nf][2] *= sc1; ctx[mi][nf][3] *= sc1;
            }
        }
        __syncwarp();

        // ---- PV: ctx[32q x 64d] += P[32 x 32] * V[32 x 64] ----
        #pragma unroll
        for (int ks = 0; ks < 4; ks++) {
            uint32_t af[2][4];
            #pragma unroll
            for (int mi = 0; mi < 2; mi++) {
                int pr = (warp * 32 + mi * 16 + g) * 36 + ks * 8 + tig;
                af[mi][0] = Ps[pr];
                af[mi][1] = Ps[pr + 8 * 36];
                af[mi][2] = Ps[pr + 4];
                af[mi][3] = Ps[pr + 8 * 36 + 4];
            }
            #pragma unroll
            for (int nf = 0; nf < 8; nf++) {
                int vr = (ks * 8 + tig) * 72 + nf * 8 + g;
                uint32_t bf[2] = { Vs[vr], Vs[vr + 4 * 72] };
                #pragma unroll
                for (int mi = 0; mi < 2; mi++)
                    mma_tf32(ctx[mi][nf], af[mi], bf);
            }
        }
        __syncthreads();
    }

    // ---- epilogue ----
    #pragma unroll
    for (int mi = 0; mi < 2; mi++) {
        float inv0 = 1.0f / lrow[mi][0];
        float inv1 = 1.0f / lrow[mi][1];
        int qp0 = qpw + mi * 16;
        float* dst0 = g_ctx + ((size_t)(bh >> 4) * S + qp0) * E + (bh & 15) * D;
        float* dst1 = dst0 + (size_t)8 * E;
        #pragma unroll
        for (int nf = 0; nf < 8; nf++) {
            int c = nf * 8 + 2 * tig;
            *(float2*)&dst0[c] = make_float2(ctx[mi][nf][0] * inv0, ctx[mi][nf][1] * inv0);
            *(float2*)&dst1[c] = make_float2(ctx[mi][nf][2] * inv1, ctx[mi][nf][3] * inv1);
        }
    }
}

// ---------------------------------------------------------------------------
extern "C" void kernel_launch(void* const* d_in, const int* in_sizes, int n_in,
                              void* d_out, int out_size)
{
    const float* x  = (const float*)d_in[0];
    const float* Wq = (const float*)d_in[1];
    const float* bq = (const float*)d_in[2];
    const float* Wk = (const float*)d_in[3];
    const float* bk = (const float*)d_in[4];
    const float* Wv = (const float*)d_in[5];
    const float* bv = (const float*)d_in[6];
    const float* Wo = (const float*)d_in[7];
    const float* bo = (const float*)d_in[8];
    float* out = (float*)d_out;

    float *q, *k, *v, *ctx;
    cudaGetSymbolAddress((void**)&q,   g_q);
    cudaGetSymbolAddress((void**)&k,   g_k);
    cudaGetSymbolAddress((void**)&v,   g_v);
    cudaGetSymbolAddress((void**)&ctx, g_ctx);

    dim3 gblk(128);
    dim3 ggrid(E / BN, M_ROWS / BM);   // (8, 64)

    tf32_gemm<<<ggrid, gblk>>>(x, Wq, bq, q, M_ROWS, E, E, 1, 0.125f);
    tf32_gemm<<<ggrid, gblk>>>(x, Wk, bk, k, M_ROWS, E, E, 1, 1.0f);
    tf32_gemm<<<ggrid, gblk>>>(x, Wv, bv, v, M_ROWS, E, E, 2, 1.0f);

    attn_mma<<<dim3(S / 128, B * H), 128>>>();

    tf32_gemm<<<ggrid, gblk>>>(ctx, Wo, bo, out, M_ROWS, E, E, 0, 1.0f);
}

// round 13
// speedup vs baseline: 1.6570x; 1.6570x over previous
#include <cuda_runtime.h>
#include <cuda_bf16.h>
#include <math.h>
#include <stdint.h>

// Problem constants
#define B     2
#define S     4096
#define E     1024
#define H     16
#define D     64
#define WIN   256
#define M_ROWS (B * S)        // 8192
#define GK    1024

// Scratch buffers
__device__ float g_q[B * H * S * D];    // [b,h,s,d]
__device__ float g_k[B * H * S * D];
__device__ float g_v[B * H * S * D];
__device__ float g_ctx[B * S * E];      // [b,s,e] (tf32-rounded values)
__device__ float g_xr[M_ROWS * E];      // tf32-rounded x
__device__ float g_wq[E * E];           // tf32-rounded weights
__device__ float g_wk[E * E];
__device__ float g_wv[E * E];
__device__ float g_wo[E * E];

// ---------------------------------------------------------------------------
__device__ __forceinline__ uint32_t f2tf32(float x) {
    uint32_t r;
    asm("cvt.rna.tf32.f32 %0, %1;" : "=r"(r) : "f"(x));
    return r;
}

__device__ __forceinline__ void mma_tf32(float d[4], const uint32_t a[4], const uint32_t b[2]) {
    asm volatile(
        "mma.sync.aligned.m16n8k8.row.col.f32.tf32.tf32.f32 "
        "{%0,%1,%2,%3}, {%4,%5,%6,%7}, {%8,%9}, {%0,%1,%2,%3};"
        : "+f"(d[0]), "+f"(d[1]), "+f"(d[2]), "+f"(d[3])
        : "r"(a[0]), "r"(a[1]), "r"(a[2]), "r"(a[3]), "r"(b[0]), "r"(b[1]));
}

__device__ __forceinline__ uint32_t smem_u32(const void* p) {
    uint32_t a;
    asm("{ .reg .u64 t; cvta.to.shared.u64 t, %1; cvt.u32.u64 %0, t; }" : "=r"(a) : "l"(p));
    return a;
}

__device__ __forceinline__ void cp16(uint32_t saddr, const void* g) {
    asm volatile("cp.async.cg.shared.global [%0], [%1], 16;" :: "r"(saddr), "l"(g) : "memory");
}
__device__ __forceinline__ void cp_commit() { asm volatile("cp.async.commit_group;" ::: "memory"); }
__device__ __forceinline__ void cp_wait0()  { asm volatile("cp.async.wait_group 0;"  ::: "memory"); }
__device__ __forceinline__ void cp_wait1()  { asm volatile("cp.async.wait_group 1;"  ::: "memory"); }

// ---------------------------------------------------------------------------
// tf32 rounding pass (rna): makes values tf32-exact so raw cp.async is lossless
// ---------------------------------------------------------------------------
__global__ void round_tf32(const float* __restrict__ in, float* __restrict__ out, int n4)
{
    int i = blockIdx.x * blockDim.x + threadIdx.x;
    if (i < n4) {
        float4 v = ((const float4*)in)[i];
        ((uint4*)out)[i] = make_uint4(f2tf32(v.x), f2tf32(v.y), f2tf32(v.z), f2tf32(v.w));
    }
}

// ---------------------------------------------------------------------------
// tf32 mma.sync GEMM with 2-stage cp.async double buffering.
// C = A @ Wt^T + bias. A,Wt pre-rounded tf32-exact fp32.
// Block 128x128x32, 256 threads (8 warps, 2m x 4n, warp tile 64x32).
// smem: As[2][128][36] + Bs[2][128][36] u32 = 72KB dynamic.
// mode 0: row-major out; mode 1: [b,h,s,d] scatter + head-rope*scale; mode 2: scatter.
// ---------------------------------------------------------------------------
#define BM 128
#define BN 128
#define BK 32
#define SSTR 36
#define NIT (GK / BK)          // 32
#define GEMM_SMEM (4 * BM * SSTR * 4)   // 73728 bytes

__global__ void __launch_bounds__(256, 2)
tf32_gemm(const float* __restrict__ A, const float* __restrict__ Wt,
          const float* __restrict__ bias, float* __restrict__ C,
          int mode, float scale)
{
    extern __shared__ uint32_t smem[];
    // layout: As[2][128][36] at 0, Bs[2][128][36] after
    uint32_t* AsBase = smem;
    uint32_t* BsBase = smem + 2 * BM * SSTR;

    const int tid  = threadIdx.x;
    const int warp = tid >> 5;
    const int lane = tid & 31;
    const int g    = lane >> 2;
    const int tig  = lane & 3;
    const int wm   = warp & 1;      // 2 m-warps, 64 rows
    const int wn   = warp >> 1;     // 4 n-warps, 32 cols

    const int m0 = blockIdx.y * BM;
    const int n0 = blockIdx.x * BN;

    const uint32_t sA = smem_u32(AsBase);
    const uint32_t sB = smem_u32(BsBase);

    float acc[4][4][4];
    #pragma unroll
    for (int mi = 0; mi < 4; mi++)
        #pragma unroll
        for (int ni = 0; ni < 4; ni++)
            #pragma unroll
            for (int r = 0; r < 4; r++) acc[mi][ni][r] = 0.f;

    // cp.async chunk mapping: 1024 16B-chunks per matrix per stage; 4 per thread.
    // chunk c: row = c>>3, col = (c&7)*4 floats.
    auto preload = [&](int it, int s) {
        const int k0 = it * BK;
        const uint32_t stgoff = (uint32_t)s * BM * SSTR * 4;
        #pragma unroll
        for (int j = 0; j < 4; j++) {
            int c   = tid + 256 * j;
            int row = c >> 3;
            int col = (c & 7) * 4;
            uint32_t so = (uint32_t)(row * SSTR + col) * 4;
            cp16(sA + stgoff + so, A  + (size_t)(m0 + row) * GK + k0 + col);
            cp16(sB + stgoff + so, Wt + (size_t)(n0 + row) * GK + k0 + col);
        }
        cp_commit();
    };

    preload(0, 0);

    for (int it = 0; it < NIT; it++) {
        const int s = it & 1;
        if (it + 1 < NIT) {
            preload(it + 1, s ^ 1);
            cp_wait1();            // stage s complete (one group still in flight)
        } else {
            cp_wait0();
        }
        __syncthreads();           // stage s visible to all warps

        const uint32_t* As = AsBase + (size_t)s * BM * SSTR;
        const uint32_t* Bs = BsBase + (size_t)s * BM * SSTR;

        #pragma unroll
        for (int ks = 0; ks < 4; ks++) {
            const int kb = ks * 8;
            uint32_t af[4][4];
            #pragma unroll
            for (int mi = 0; mi < 4; mi++) {
                int rm = wm * 64 + mi * 16;
                af[mi][0] = As[(rm + g)     * SSTR + kb + tig];
                af[mi][1] = As[(rm + g + 8) * SSTR + kb + tig];
                af[mi][2] = As[(rm + g)     * SSTR + kb + tig + 4];
                af[mi][3] = As[(rm + g + 8) * SSTR + kb + tig + 4];
            }
            uint32_t bf[4][2];
            #pragma unroll
            for (int ni = 0; ni < 4; ni++) {
                int cb = wn * 32 + ni * 8;
                bf[ni][0] = Bs[(cb + g) * SSTR + kb + tig];
                bf[ni][1] = Bs[(cb + g) * SSTR + kb + tig + 4];
            }
            #pragma unroll
            for (int mi = 0; mi < 4; mi++)
                #pragma unroll
                for (int ni = 0; ni < 4; ni++)
                    mma_tf32(acc[mi][ni], af[mi], bf[ni]);
        }
        __syncthreads();           // all reads of stage s done before it's refilled
    }

    // ---------------- epilogue ----------------
    const float Lc = 13.287712379549449f / 32.0f;  // log2(10000)/32
    #pragma unroll
    for (int mi = 0; mi < 4; mi++) {
        #pragma unroll
        for (int ni = 0; ni < 4; ni++) {
            int c0 = n0 + wn * 32 + ni * 8 + 2 * tig;
            float bias0 = bias[c0];
            float bias1 = bias[c0 + 1];
            #pragma unroll
            for (int rr = 0; rr < 2; rr++) {
                int n = m0 + wm * 64 + mi * 16 + g + rr * 8;
                float x0 = acc[mi][ni][2 * rr + 0] + bias0;
                float x1 = acc[mi][ni][2 * rr + 1] + bias1;
                float o0, o1;
                if (mode == 1) {
                    int hh = c0 >> 6;
                    int mm0 = c0 & 31;
                    int mm1 = (c0 + 1) & 31;
                    float f0 = exp2f(-(float)mm0 * Lc);
                    float f1 = exp2f(-(float)mm1 * Lc);
                    float s0, cs0, s1, cs1;
                    sincosf((float)hh * f0, &s0, &cs0);
                    sincosf((float)hh * f1, &s1, &cs1);
                    o0 = (x0 * cs0 - x1 * s0) * scale;
                    o1 = (x1 * cs1 + x0 * s1) * scale;
                } else {
                    o0 = x0;
                    o1 = x1;
                }
                if (mode == 0) {
                    *(float2*)&C[(size_t)n * E + c0] = make_float2(o0, o1);
                } else {
                    int bb = n >> 12;
                    int sr = n & 4095;
                    int hh = c0 >> 6;
                    int dd = c0 & 63;
                    float* dst = C + ((size_t)((bb << 4) + hh) * 4096 + sr) * 64 + dd;
                    *(float2*)dst = make_float2(o0, o1);
                }
            }
        }
    }
}

// ---------------------------------------------------------------------------
// Flash attention, tf32 MMA (R7 structure; epilogue stores tf32-rounded ctx).
// 128-query blocks, 4 warps; 20 key tiles of 32; V row-major stride 72.
// ---------------------------------------------------------------------------
#define AT_VS 2176
#define AT_PS 4480
#define AT_SM 9088

__global__ void __launch_bounds__(128)
attn_mma()
{
    __shared__ uint32_t sm[AT_SM];

    const int t    = threadIdx.x;
    const int lane = t & 31;
    const int warp = t >> 5;
    const int g    = lane >> 2;
    const int tig  = lane & 3;
    const int qb   = blockIdx.x;
    const int bh   = blockIdx.y;
    const int q0   = qb * 128;

    const float* qg = g_q + (size_t)bh * S * D;
    const float* kg = g_k + (size_t)bh * S * D;
    const float* vg = g_v + (size_t)bh * S * D;

    {
        uint32_t* Qs = sm;   // [128][68]
        const float4* src = (const float4*)(qg + (size_t)(q0 + t) * D);
        #pragma unroll
        for (int i = 0; i < 16; i++) {
            float4 v4 = src[i];
            *(uint4*)&Qs[t * 68 + 4 * i] =
                make_uint4(f2tf32(v4.x), f2tf32(v4.y), f2tf32(v4.z), f2tf32(v4.w));
        }
    }
    __syncthreads();
    uint32_t qf[2][8][4];
    {
        const uint32_t* Qs = sm;
        #pragma unroll
        for (int mi = 0; mi < 2; mi++) {
            int r0 = (warp * 32 + mi * 16 + g) * 68;
            int r1 = r0 + 8 * 68;
            #pragma unroll
            for (int ks = 0; ks < 8; ks++) {
                int c = ks * 8 + tig;
                qf[mi][ks][0] = Qs[r0 + c];
                qf[mi][ks][1] = Qs[r1 + c];
                qf[mi][ks][2] = Qs[r0 + c + 4];
                qf[mi][ks][3] = Qs[r1 + c + 4];
            }
        }
    }
    __syncthreads();

    uint32_t* Ks = sm;            // [32][68]
    uint32_t* Vs = sm + AT_VS;    // [32][72] row-major
    uint32_t* Ps = sm + AT_PS;    // [128][36]

    float ctx[2][8][4];
    #pragma unroll
    for (int mi = 0; mi < 2; mi++)
        #pragma unroll
        for (int nf = 0; nf < 8; nf++)
            #pragma unroll
            for (int c = 0; c < 4; c++) ctx[mi][nf][c] = 0.f;
    float mrow[2][2], lrow[2][2];
    #pragma unroll
    for (int mi = 0; mi < 2; mi++) {
        mrow[mi][0] = mrow[mi][1] = -3.0e38f;
        lrow[mi][0] = lrow[mi][1] = 0.f;
    }

    const int qpw = q0 + warp * 32 + g;

    int kbase = q0 - 256;
    for (int kt = 0; kt < 20; kt++, kbase += 32) {
        {
            int lr = t >> 2;
            int lc = (t & 3) * 16;
            int kr = kbase + lr;
            bool ok = (kr >= 0) && (kr < S);
            const float4* kp = (const float4*)(kg + (size_t)(ok ? kr : 0) * D + lc);
            const float4* vp = (const float4*)(vg + (size_t)(ok ? kr : 0) * D + lc);
            float4 z4 = make_float4(0.f, 0.f, 0.f, 0.f);
            #pragma unroll
            for (int i = 0; i < 4; i++) {
                float4 kv = ok ? kp[i] : z4;
                float4 vv = ok ? vp[i] : z4;
                *(uint4*)&Ks[lr * 68 + lc + 4 * i] =
                    make_uint4(f2tf32(kv.x), f2tf32(kv.y), f2tf32(kv.z), f2tf32(kv.w));
                *(uint4*)&Vs[lr * 72 + lc + 4 * i] =
                    make_uint4(f2tf32(vv.x), f2tf32(vv.y), f2tf32(vv.z), f2tf32(vv.w));
            }
        }
        __syncthreads();

        float sc[2][4][4];
        #pragma unroll
        for (int mi = 0; mi < 2; mi++)
            #pragma unroll
            for (int nf = 0; nf < 4; nf++)
                #pragma unroll
                for (int c = 0; c < 4; c++) sc[mi][nf][c] = 0.f;

        #pragma unroll
        for (int ks = 0; ks < 8; ks++) {
            uint32_t bf[4][2];
            #pragma unroll
            for (int nf = 0; nf < 4; nf++) {
                int r = (nf * 8 + g) * 68 + ks * 8 + tig;
                bf[nf][0] = Ks[r];
                bf[nf][1] = Ks[r + 4];
            }
            #pragma unroll
            for (int mi = 0; mi < 2; mi++)
                #pragma unroll
                for (int nf = 0; nf < 4; nf++)
                    mma_tf32(sc[mi][nf], qf[mi][ks], bf[nf]);
        }

        #pragma unroll
        for (int mi = 0; mi < 2; mi++) {
            const int qp0 = qpw + mi * 16;
            float mx0 = -3.0e38f, mx1 = -3.0e38f;
            #pragma unroll
            for (int nf = 0; nf < 4; nf++) {
                int kp0 = kbase + nf * 8 + 2 * tig;
                #pragma unroll
                for (int c = 0; c < 4; c++) {
                    int kpos = kp0 + (c & 1);
                    int qpos = qp0 + (c >> 1) * 8;
                    int dlt  = kpos - qpos;
                    bool valid = (dlt >= -WIN) && (dlt <= WIN) && (kpos >= 0) && (kpos < S);
                    if (!valid) sc[mi][nf][c] = -3.0e38f;
                }
                mx0 = fmaxf(mx0, fmaxf(sc[mi][nf][0], sc[mi][nf][1]));
                mx1 = fmaxf(mx1, fmaxf(sc[mi][nf][2], sc[mi][nf][3]));
            }
            mx0 = fmaxf(mx0, __shfl_xor_sync(0xffffffffu, mx0, 1));
            mx0 = fmaxf(mx0, __shfl_xor_sync(0xffffffffu, mx0, 2));
            mx1 = fmaxf(mx1, __shfl_xor_sync(0xffffffffu, mx1, 1));
            mx1 = fmaxf(mx1, __shfl_xor_sync(0xffffffffu, mx1, 2));

            float mn0 = fmaxf(fmaxf(mrow[mi][0], mx0), -1.0e30f);
            float mn1 = fmaxf(fmaxf(mrow[mi][1], mx1), -1.0e30f);
            float sc0 = __expf(mrow[mi][0] - mn0);
            float sc1 = __expf(mrow[mi][1] - mn1);
            mrow[mi][0] = mn0; mrow[mi][1] = mn1;

            float rs0 = 0.f, rs1 = 0.f;
            const int prb = (warp * 32 + mi * 16 + g) * 36;
            #pragma unroll
            for (int nf = 0; nf < 4; nf++) {
                float p0 = __expf(sc[mi][nf][0] - mn0);
                float p1 = __expf(sc[mi][nf][1] - mn0);
                float p2 = __expf(sc[mi][nf][2] - mn1);
                float p3 = __expf(sc[mi][nf][3] - mn1);
                rs0 += p0 + p1;
                rs1 += p2 + p3;
                int cofs = nf * 8 + 2 * tig;
                *(uint2*)&Ps[prb + cofs]          = make_uint2(f2tf32(p0), f2tf32(p1));
                *(uint2*)&Ps[prb + 8 * 36 + cofs] = make_uint2(f2tf32(p2), f2tf32(p3));
            }
            rs0 += __shfl_xor_sync(0xffffffffu, rs0, 1);
            rs0 += __shfl_xor_sync(0xffffffffu, rs0, 2);
            rs1 += __shfl_xor_sync(0xffffffffu, rs1, 1);
            rs1 += __shfl_xor_sync(0xffffffffu, rs1, 2);
            lrow[mi][0] = lrow[mi][0] * sc0 + rs0;
            lrow[mi][1] = lrow[mi][1] * sc1 + rs1;

            #pragma unroll
            for (int nf = 0; nf < 8; nf++) {
                ctx[mi][nf][0] *= sc0; ctx[mi][nf][1] *= sc0;
                ctx[mi][nf][2] *= sc1; ctx[mi][nf][3] *= sc1;
            }
        }
        __syncwarp();

        #pragma unroll
        for (int ks = 0; ks < 4; ks++) {
            uint32_t af[2][4];
            #pragma unroll
            for (int mi = 0; mi < 2; mi++) {
                int pr = (warp * 32 + mi * 16 + g) * 36 + ks * 8 + tig;
                af[mi][0] = Ps[pr];
                af[mi][1] = Ps[pr + 8 * 36];
                af[mi][2] = Ps[pr + 4];
                af[mi][3] = Ps[pr + 8 * 36 + 4];
            }
            #pragma unroll
            for (int nf = 0; nf < 8; nf++) {
                int vr = (ks * 8 + tig) * 72 + nf * 8 + g;
                uint32_t bf[2] = { Vs[vr], Vs[vr + 4 * 72] };
                #pragma unroll
                for (int mi = 0; mi < 2; mi++)
                    mma_tf32(ctx[mi][nf], af[mi], bf);
            }
        }
        __syncthreads();
    }

    // epilogue: store tf32-rounded ctx (lossless for cp.async raw feed into O-proj)
    #pragma unroll
    for (int mi = 0; mi < 2; mi++) {
        float inv0 = 1.0f / lrow[mi][0];
        float inv1 = 1.0f / lrow[mi][1];
        int qp0 = qpw + mi * 16;
        float* dst0 = g_ctx + ((size_t)(bh >> 4) * S + qp0) * E + (bh & 15) * D;
        float* dst1 = dst0 + (size_t)8 * E;
        #pragma unroll
        for (int nf = 0; nf < 8; nf++) {
            int c = nf * 8 + 2 * tig;
            *(float2*)&dst0[c] = make_float2(
                __uint_as_float(f2tf32(ctx[mi][nf][0] * inv0)),
                __uint_as_float(f2tf32(ctx[mi][nf][1] * inv0)));
            *(float2*)&dst1[c] = make_float2(
                __uint_as_float(f2tf32(ctx[mi][nf][2] * inv1)),
                __uint_as_float(f2tf32(ctx[mi][nf][3] * inv1)));
        }
    }
}

// ---------------------------------------------------------------------------
extern "C" void kernel_launch(void* const* d_in, const int* in_sizes, int n_in,
                              void* d_out, int out_size)
{
    const float* x  = (const float*)d_in[0];
    const float* Wq = (const float*)d_in[1];
    const float* bq = (const float*)d_in[2];
    const float* Wk = (const float*)d_in[3];
    const float* bk = (const float*)d_in[4];
    const float* Wv = (const float*)d_in[5];
    const float* bv = (const float*)d_in[6];
    const float* Wo = (const float*)d_in[7];
    const float* bo = (const float*)d_in[8];
    float* out = (float*)d_out;

    float *q, *k, *v, *ctx, *xr, *wq, *wk, *wv, *wo;
    cudaGetSymbolAddress((void**)&q,   g_q);
    cudaGetSymbolAddress((void**)&k,   g_k);
    cudaGetSymbolAddress((void**)&v,   g_v);
    cudaGetSymbolAddress((void**)&ctx, g_ctx);
    cudaGetSymbolAddress((void**)&xr,  g_xr);
    cudaGetSymbolAddress((void**)&wq,  g_wq);
    cudaGetSymbolAddress((void**)&wk,  g_wk);
    cudaGetSymbolAddress((void**)&wv,  g_wv);
    cudaGetSymbolAddress((void**)&wo,  g_wo);

    cudaFuncSetAttribute(tf32_gemm, cudaFuncAttributeMaxDynamicSharedMemorySize, GEMM_SMEM);

    // tf32-exact rounding passes (so cp.async raw loads are lossless)
    const int XN4 = M_ROWS * E / 4;
    const int WN4 = E * E / 4;
    round_tf32<<<(XN4 + 255) / 256, 256>>>(x,  xr, XN4);
    round_tf32<<<(WN4 + 255) / 256, 256>>>(Wq, wq, WN4);
    round_tf32<<<(WN4 + 255) / 256, 256>>>(Wk, wk, WN4);
    round_tf32<<<(WN4 + 255) / 256, 256>>>(Wv, wv, WN4);
    round_tf32<<<(WN4 + 255) / 256, 256>>>(Wo, wo, WN4);

    dim3 ggrid(E / BN, M_ROWS / BM);    // (8, 64)
    tf32_gemm<<<ggrid, 256, GEMM_SMEM>>>(xr, wq, bq, q, 1, 0.125f);  // Q: rope + 1/sqrt(d)
    tf32_gemm<<<ggrid, 256, GEMM_SMEM>>>(xr, wk, bk, k, 1, 1.0f);    // K: rope
    tf32_gemm<<<ggrid, 256, GEMM_SMEM>>>(xr, wv, bv, v, 2, 1.0f);    // V: scatter

    attn_mma<<<dim3(S / 128, B * H), 128>>>();

    tf32_gemm<<<ggrid, 256, GEMM_SMEM>>>(ctx, wo, bo, out, 0, 1.0f); // O projection
}

// round 16
// speedup vs baseline: 3.1564x; 1.9049x over previous
#include <cuda_runtime.h>
#include <cuda_fp16.h>
#include <math.h>
#include <stdint.h>

// Problem constants
#define B     2
#define S     4096
#define E     1024
#define H     16
#define D     64
#define WIN   256
#define M_ROWS (B * S)        // 8192
#define GK    1024

// Scratch buffers (half precision)
__device__ __half g_q[B * H * S * D];    // [b,h,s,d]
__device__ __half g_k[B * H * S * D];
__device__ __half g_v[B * H * S * D];
__device__ __half g_ctx[B * S * E];      // [b,s,e]
__device__ __half g_xh[M_ROWS * E];      // half x
__device__ __half g_wq[E * E];           // half weights
__device__ __half g_wk[E * E];
__device__ __half g_wv[E * E];
__device__ __half g_wo[E * E];

// ---------------------------------------------------------------------------
__device__ __forceinline__ void mma_f16(float d[4], const uint32_t a[4], const uint32_t b[2]) {
    asm volatile(
        "mma.sync.aligned.m16n8k16.row.col.f32.f16.f16.f32 "
        "{%0,%1,%2,%3}, {%4,%5,%6,%7}, {%8,%9}, {%0,%1,%2,%3};"
        : "+f"(d[0]), "+f"(d[1]), "+f"(d[2]), "+f"(d[3])
        : "r"(a[0]), "r"(a[1]), "r"(a[2]), "r"(a[3]), "r"(b[0]), "r"(b[1]));
}

__device__ __forceinline__ uint32_t smem_u32(const void* p) {
    uint32_t a;
    asm("{ .reg .u64 t; cvta.to.shared.u64 t, %1; cvt.u32.u64 %0, t; }" : "=r"(a) : "l"(p));
    return a;
}

__device__ __forceinline__ void cp16(uint32_t saddr, const void* g) {
    asm volatile("cp.async.cg.shared.global [%0], [%1], 16;" :: "r"(saddr), "l"(g) : "memory");
}
__device__ __forceinline__ void cp_commit() { asm volatile("cp.async.commit_group;" ::: "memory"); }
__device__ __forceinline__ void cp_wait0()  { asm volatile("cp.async.wait_group 0;"  ::: "memory"); }
__device__ __forceinline__ void cp_wait1()  { asm volatile("cp.async.wait_group 1;"  ::: "memory"); }

__device__ __forceinline__ uint32_t pack_h2(float a, float b) {
    __half2 h = __floats2half2_rn(a, b);
    return *(uint32_t*)&h;
}

// ---------------------------------------------------------------------------
// fp32 -> fp16 conversion pass (8 elements/thread)
// ---------------------------------------------------------------------------
__global__ void to_half(const float* __restrict__ in, __half* __restrict__ out, int n8)
{
    int i = blockIdx.x * blockDim.x + threadIdx.x;
    if (i < n8) {
        float4 a = ((const float4*)in)[2 * i];
        float4 b = ((const float4*)in)[2 * i + 1];
        uint4 o;
        o.x = pack_h2(a.x, a.y);
        o.y = pack_h2(a.z, a.w);
        o.z = pack_h2(b.x, b.y);
        o.w = pack_h2(b.z, b.w);
        ((uint4*)out)[i] = o;
    }
}

// ---------------------------------------------------------------------------
// fp16 mma.sync GEMM with 2-stage cp.async double buffering.
// C = A @ Wt^T + bias (A,Wt half). Block 128x128, K-chunk 64 halves.
// 256 threads (8 warps, 2m x 4n, warp tile 64x32), m16n8k16 f16/f32-acc.
// smem u32 view: As[2][128][36] + Bs[2][128][36] = 72KB.
// mode 0: float row-major out; mode 1: half [b,h,s,d] scatter + rope*scale;
// mode 2: half scatter.
// ---------------------------------------------------------------------------
#define BM 128
#define BN 128
#define SSTR 36
#define NIT 16                 // 1024 / 64
#define GEMM_SMEM (4 * BM * SSTR * 4)   // 73728 bytes

__global__ void __launch_bounds__(256, 2)
f16_gemm(const __half* __restrict__ A, const __half* __restrict__ Wt,
         const float* __restrict__ bias, void* __restrict__ Cv,
         int mode, float scale)
{
    extern __shared__ uint32_t smem[];
    uint32_t* AsBase = smem;
    uint32_t* BsBase = smem + 2 * BM * SSTR;

    const int tid  = threadIdx.x;
    const int warp = tid >> 5;
    const int lane = tid & 31;
    const int g    = lane >> 2;
    const int tig  = lane & 3;
    const int wm   = warp & 1;
    const int wn   = warp >> 1;

    const int m0 = blockIdx.y * BM;
    const int n0 = blockIdx.x * BN;

    const uint32_t sA = smem_u32(AsBase);
    const uint32_t sB = smem_u32(BsBase);

    float acc[4][4][4];
    #pragma unroll
    for (int mi = 0; mi < 4; mi++)
        #pragma unroll
        for (int ni = 0; ni < 4; ni++)
            #pragma unroll
            for (int r = 0; r < 4; r++) acc[mi][ni][r] = 0.f;

    // per stage per matrix: 128 rows x 128B = 1024 16B-chunks; 4/thread.
    auto preload = [&](int it, int s) {
        const int k0 = it * 64;
        const uint32_t stg = (uint32_t)s * BM * SSTR * 4;
        #pragma unroll
        for (int j = 0; j < 4; j++) {
            int c   = tid + 256 * j;
            int row = c >> 3;
            int cc  = c & 7;
            uint32_t so = (uint32_t)(row * SSTR + cc * 4) * 4;
            cp16(sA + stg + so, A  + (size_t)(m0 + row) * GK + k0 + cc * 8);
            cp16(sB + stg + so, Wt + (size_t)(n0 + row) * GK + k0 + cc * 8);
        }
        cp_commit();
    };

    preload(0, 0);

    for (int it = 0; it < NIT; it++) {
        const int s = it & 1;
        if (it + 1 < NIT) {
            preload(it + 1, s ^ 1);
            cp_wait1();
        } else {
            cp_wait0();
        }
        __syncthreads();

        const uint32_t* As = AsBase + (size_t)s * BM * SSTR;
        const uint32_t* Bs = BsBase + (size_t)s * BM * SSTR;

        #pragma unroll
        for (int ks = 0; ks < 4; ks++) {
            const int kb = ks * 8;
            uint32_t af[4][4];
            #pragma unroll
            for (int mi = 0; mi < 4; mi++) {
                int rm = wm * 64 + mi * 16;
                af[mi][0] = As[(rm + g)     * SSTR + kb + tig];
                af[mi][1] = As[(rm + g + 8) * SSTR + kb + tig];
                af[mi][2] = As[(rm + g)     * SSTR + kb + tig + 4];
                af[mi][3] = As[(rm + g + 8) * SSTR + kb + tig + 4];
            }
            uint32_t bf[4][2];
            #pragma unroll
            for (int ni = 0; ni < 4; ni++) {
                int cb = wn * 32 + ni * 8;
                bf[ni][0] = Bs[(cb + g) * SSTR + kb + tig];
                bf[ni][1] = Bs[(cb + g) * SSTR + kb + tig + 4];
            }
            #pragma unroll
            for (int mi = 0; mi < 4; mi++)
                #pragma unroll
                for (int ni = 0; ni < 4; ni++)
                    mma_f16(acc[mi][ni], af[mi], bf[ni]);
        }
        __syncthreads();
    }

    // ---------------- epilogue ----------------
    const float Lc = 13.287712379549449f / 32.0f;  // log2(10000)/32
    #pragma unroll
    for (int mi = 0; mi < 4; mi++) {
        #pragma unroll
        for (int ni = 0; ni < 4; ni++) {
            int c0 = n0 + wn * 32 + ni * 8 + 2 * tig;
            float bias0 = bias[c0];
            float bias1 = bias[c0 + 1];
            #pragma unroll
            for (int rr = 0; rr < 2; rr++) {
                int n = m0 + wm * 64 + mi * 16 + g + rr * 8;
                float x0 = acc[mi][ni][2 * rr + 0] + bias0;
                float x1 = acc[mi][ni][2 * rr + 1] + bias1;
                float o0, o1;
                if (mode == 1) {
                    int hh = c0 >> 6;
                    int mm0 = c0 & 31;
                    int mm1 = (c0 + 1) & 31;
                    float f0 = exp2f(-(float)mm0 * Lc);
                    float f1 = exp2f(-(float)mm1 * Lc);
                    float s0, cs0, s1, cs1;
                    sincosf((float)hh * f0, &s0, &cs0);
                    sincosf((float)hh * f1, &s1, &cs1);
                    o0 = (x0 * cs0 - x1 * s0) * scale;
                    o1 = (x1 * cs1 + x0 * s1) * scale;
                } else {
                    o0 = x0;
                    o1 = x1;
                }
                if (mode == 0) {
                    float* C = (float*)Cv;
                    *(float2*)&C[(size_t)n * E + c0] = make_float2(o0, o1);
                } else {
                    __half* C = (__half*)Cv;
                    int bb = n >> 12;
                    int sr = n & 4095;
                    int hh = c0 >> 6;
                    int dd = c0 & 63;
                    __half* dst = C + ((size_t)((bb << 4) + hh) * 4096 + sr) * 64 + dd;
                    *(uint32_t*)dst = pack_h2(o0, o1);
                }
            }
        }
    }
}

// ---------------------------------------------------------------------------
// Flash attention, fp16 MMA. 128-query blocks, 4 warps (32 q each, mi=0,1).
// 20 key tiles of 32; fully-invalid tiles skipped (uniform per block).
// smem u32: Ks [32][36] @0, Vt [16 keypair][72 d+pad] @1152, Ps [128][20] @2304.
// Q staged at base ([128][36]=4608 <= 4864) before K/V use.
// ---------------------------------------------------------------------------
#define AT_KS 0
#define AT_VT 1152
#define AT_PS 2304
#define AT_SM 4864

__global__ void __launch_bounds__(128)
attn_mma()
{
    __shared__ uint32_t sm[AT_SM];

    const int t    = threadIdx.x;
    const int lane = t & 31;
    const int warp = t >> 5;
    const int g    = lane >> 2;
    const int tig  = lane & 3;
    const int qb   = blockIdx.x;
    const int bh   = blockIdx.y;
    const int q0   = qb * 128;

    const __half* qg = g_q + (size_t)bh * S * D;
    const __half* kg = g_k + (size_t)bh * S * D;
    const __half* vg = g_v + (size_t)bh * S * D;

    const uint32_t smb = smem_u32(sm);

    // ---- stage Q via cp.async: row t, 64 halves = 8 chunks ----
    {
        #pragma unroll
        for (int c = 0; c < 8; c++)
            cp16(smb + (uint32_t)(t * 36 + c * 4) * 4, qg + (size_t)(q0 + t) * D + c * 8);
        cp_commit();
        cp_wait0();
    }
    __syncthreads();
    uint32_t qf[2][4][4];
    {
        const uint32_t* Qs = sm;
        #pragma unroll
        for (int mi = 0; mi < 2; mi++) {
            int r0 = (warp * 32 + mi * 16 + g) * 36;
            int r1 = r0 + 8 * 36;
            #pragma unroll
            for (int ks = 0; ks < 4; ks++) {
                int c = ks * 8 + tig;
                qf[mi][ks][0] = Qs[r0 + c];
                qf[mi][ks][1] = Qs[r1 + c];
                qf[mi][ks][2] = Qs[r0 + c + 4];
                qf[mi][ks][3] = Qs[r1 + c + 4];
            }
        }
    }
    __syncthreads();

    uint32_t* Ks = sm + AT_KS;    // [32 key][36]  (d-halves)
    uint32_t* Vt = sm + AT_VT;    // [16 keypair][72] (d minor, half2 of key pair)
    uint32_t* Ps = sm + AT_PS;    // [128 q][20]   (key-pair halves)

    float ctx[2][8][4];
    #pragma unroll
    for (int mi = 0; mi < 2; mi++)
        #pragma unroll
        for (int nf = 0; nf < 8; nf++)
            #pragma unroll
            for (int c = 0; c < 4; c++) ctx[mi][nf][c] = 0.f;
    float mrow[2][2], lrow[2][2];
    #pragma unroll
    for (int mi = 0; mi < 2; mi++) {
        mrow[mi][0] = mrow[mi][1] = -3.0e38f;
        lrow[mi][0] = lrow[mi][1] = 0.f;
    }

    const int qpw = q0 + warp * 32 + g;

    int kbase = q0 - 256;
    for (int kt = 0; kt < 20; kt++, kbase += 32) {
        if (kbase < 0 || kbase >= S) continue;   // uniform across block

        // ---- K tile via cp.async (raw half) ----
        {
            int row = t >> 2;
            int cc  = t & 3;
            uint32_t so = smb + AT_KS * 4 + (uint32_t)(row * 36 + cc * 8) * 4;
            const __half* src = kg + (size_t)(kbase + row) * D + cc * 16;
            cp16(so,      src);
            cp16(so + 16, src + 8);
            cp_commit();
        }
        // ---- V transposed into key-pair half2: thread kp=t>>3, dch=t&7 ----
        {
            int kp  = t >> 3;
            int dch = t & 7;
            const uint4* vp0 = (const uint4*)(vg + (size_t)(kbase + 2 * kp)     * D + dch * 8);
            const uint4* vp1 = (const uint4*)(vg + (size_t)(kbase + 2 * kp + 1) * D + dch * 8);
            uint4 r0 = *vp0;
            uint4 r1 = *vp1;
            const ushort* h0 = (const ushort*)&r0;
            const ushort* h1 = (const ushort*)&r1;
            uint4 o0, o1;
            o0.x = h0[0] | ((uint32_t)h1[0] << 16);
            o0.y = h0[1] | ((uint32_t)h1[1] << 16);
            o0.z = h0[2] | ((uint32_t)h1[2] << 16);
            o0.w = h0[3] | ((uint32_t)h1[3] << 16);
            o1.x = h0[4] | ((uint32_t)h1[4] << 16);
            o1.y = h0[5] | ((uint32_t)h1[5] << 16);
            o1.z = h0[6] | ((uint32_t)h1[6] << 16);
            o1.w = h0[7] | ((uint32_t)h1[7] << 16);
            *(uint4*)&Vt[kp * 72 + dch * 8]     = o0;
            *(uint4*)&Vt[kp * 72 + dch * 8 + 4] = o1;
        }
        cp_wait0();
        __syncthreads();

        // ---- QK^T: per warp 32q x 32k, 4 ksteps of k16 ----
        float sc[2][4][4];
        #pragma unroll
        for (int mi = 0; mi < 2; mi++)
            #pragma unroll
            for (int nf = 0; nf < 4; nf++)
                #pragma unroll
                for (int c = 0; c < 4; c++) sc[mi][nf][c] = 0.f;

        #pragma unroll
        for (int ks = 0; ks < 4; ks++) {
            uint32_t bf[4][2];
            #pragma unroll
            for (int nf = 0; nf < 4; nf++) {
                int r = (nf * 8 + g) * 36 + ks * 8 + tig;
                bf[nf][0] = Ks[r];
                bf[nf][1] = Ks[r + 4];
            }
            #pragma unroll
            for (int mi = 0; mi < 2; mi++)
                #pragma unroll
                for (int nf = 0; nf < 4; nf++)
                    mma_f16(sc[mi][nf], qf[mi][ks], bf[nf]);
        }

        // ---- window mask + online softmax + P store ----
        #pragma unroll
        for (int mi = 0; mi < 2; mi++) {
            const int qp0 = qpw + mi * 16;
            float mx0 = -3.0e38f, mx1 = -3.0e38f;
            #pragma unroll
            for (int nf = 0; nf < 4; nf++) {
                int kp0 = kbase + nf * 8 + 2 * tig;
                #pragma unroll
                for (int c = 0; c < 4; c++) {
                    int kpos = kp0 + (c & 1);
                    int qpos = qp0 + (c >> 1) * 8;
                    int dlt  = kpos - qpos;
                    if (dlt < -WIN || dlt > WIN) sc[mi][nf][c] = -3.0e38f;
                }
                mx0 = fmaxf(mx0, fmaxf(sc[mi][nf][0], sc[mi][nf][1]));
                mx1 = fmaxf(mx1, fmaxf(sc[mi][nf][2], sc[mi][nf][3]));
            }
            mx0 = fmaxf(mx0, __shfl_xor_sync(0xffffffffu, mx0, 1));
            mx0 = fmaxf(mx0, __shfl_xor_sync(0xffffffffu, mx0, 2));
            mx1 = fmaxf(mx1, __shfl_xor_sync(0xffffffffu, mx1, 1));
            mx1 = fmaxf(mx1, __shfl_xor_sync(0xffffffffu, mx1, 2));

            float mn0 = fmaxf(fmaxf(mrow[mi][0], mx0), -1.0e30f);
            float mn1 = fmaxf(fmaxf(mrow[mi][1], mx1), -1.0e30f);
            float sc0 = __expf(mrow[mi][0] - mn0);
            float sc1 = __expf(mrow[mi][1] - mn1);
            mrow[mi][0] = mn0; mrow[mi][1] = mn1;

            float rs0 = 0.f, rs1 = 0.f;
            const int row0 = (warp * 32 + mi * 16 + g) * 20;
            const int row1 = row0 + 8 * 20;
            #pragma unroll
            for (int nf = 0; nf < 4; nf++) {
                float p0 = __expf(sc[mi][nf][0] - mn0);
                float p1 = __expf(sc[mi][nf][1] - mn0);
                float p2 = __expf(sc[mi][nf][2] - mn1);
                float p3 = __expf(sc[mi][nf][3] - mn1);
                rs0 += p0 + p1;
                rs1 += p2 + p3;
                Ps[row0 + nf * 4 + tig] = pack_h2(p0, p1);
                Ps[row1 + nf * 4 + tig] = pack_h2(p2, p3);
            }
            rs0 += __shfl_xor_sync(0xffffffffu, rs0, 1);
            rs0 += __shfl_xor_sync(0xffffffffu, rs0, 2);
            rs1 += __shfl_xor_sync(0xffffffffu, rs1, 1);
            rs1 += __shfl_xor_sync(0xffffffffu, rs1, 2);
            lrow[mi][0] = lrow[mi][0] * sc0 + rs0;
            lrow[mi][1] = lrow[mi][1] * sc1 + rs1;

            #pragma unroll
            for (int nf = 0; nf < 8; nf++) {
                ctx[mi][nf][0] *= sc0; ctx[mi][nf][1] *= sc0;
                ctx[mi][nf][2] *= sc1; ctx[mi][nf][3] *= sc1;
            }
        }
        __syncwarp();

        // ---- PV: ctx[32q x 64d] += P[32 x 32] * V[32 x 64], 2 ksteps of k16 ----
        #pragma unroll
        for (int ks = 0; ks < 2; ks++) {
            uint32_t af[2][4];
            #pragma unroll
            for (int mi = 0; mi < 2; mi++) {
                int r0 = (warp * 32 + mi * 16 + g) * 20 + ks * 8 + tig;
                int r1 = r0 + 8 * 20;
                af[mi][0] = Ps[r0];
                af[mi][1] = Ps[r1];
                af[mi][2] = Ps[r0 + 4];
                af[mi][3] = Ps[r1 + 4];
            }
            #pragma unroll
            for (int nf = 0; nf < 8; nf++) {
                int n = nf * 8 + g;
                uint32_t bf[2] = { Vt[(8 * ks + tig) * 72 + n],
                                   Vt[(8 * ks + tig + 4) * 72 + n] };
                #pragma unroll
                for (int mi = 0; mi < 2; mi++)
                    mma_f16(ctx[mi][nf], af[mi], bf);
            }
        }
        __syncthreads();
    }

    // ---- epilogue: half ctx ----
    #pragma unroll
    for (int mi = 0; mi < 2; mi++) {
        float inv0 = 1.0f / lrow[mi][0];
        float inv1 = 1.0f / lrow[mi][1];
        int qp0 = qpw + mi * 16;
        __half* dst0 = g_ctx + ((size_t)(bh >> 4) * S + qp0) * E + (bh & 15) * D;
        __half* dst1 = dst0 + (size_t)8 * E;
        #pragma unroll
        for (int nf = 0; nf < 8; nf++) {
            int c = nf * 8 + 2 * tig;
            *(uint32_t*)&dst0[c] = pack_h2(ctx[mi][nf][0] * inv0, ctx[mi][nf][1] * inv0);
            *(uint32_t*)&dst1[c] = pack_h2(ctx[mi][nf][2] * inv1, ctx[mi][nf][3] * inv1);
        }
    }
}

// ---------------------------------------------------------------------------
extern "C" void kernel_launch(void* const* d_in, const int* in_sizes, int n_in,
                              void* d_out, int out_size)
{
    const float* x  = (const float*)d_in[0];
    const float* Wq = (const float*)d_in[1];
    const float* bq = (const float*)d_in[2];
    const float* Wk = (const float*)d_in[3];
    const float* bk = (const float*)d_in[4];
    const float* Wv = (const float*)d_in[5];
    const float* bv = (const float*)d_in[6];
    const float* Wo = (const float*)d_in[7];
    const float* bo = (const float*)d_in[8];
    float* out = (float*)d_out;

    __half *q, *k, *v, *ctx, *xh, *wq, *wk, *wv, *wo;
    cudaGetSymbolAddress((void**)&q,   g_q);
    cudaGetSymbolAddress((void**)&k,   g_k);
    cudaGetSymbolAddress((void**)&v,   g_v);
    cudaGetSymbolAddress((void**)&ctx, g_ctx);
    cudaGetSymbolAddress((void**)&xh,  g_xh);
    cudaGetSymbolAddress((void**)&wq,  g_wq);
    cudaGetSymbolAddress((void**)&wk,  g_wk);
    cudaGetSymbolAddress((void**)&wv,  g_wv);
    cudaGetSymbolAddress((void**)&wo,  g_wo);

    cudaFuncSetAttribute(f16_gemm, cudaFuncAttributeMaxDynamicSharedMemorySize, GEMM_SMEM);

    // fp32 -> fp16 conversion passes
    const int XN8 = M_ROWS * E / 8;       // 1,048,576
    const int WN8 = E * E / 8;            // 131,072
    to_half<<<(XN8 + 255) / 256, 256>>>(x,  xh, XN8);
    to_half<<<(WN8 + 255) / 256, 256>>>(Wq, wq, WN8);
    to_half<<<(WN8 + 255) / 256, 256>>>(Wk, wk, WN8);
    to_half<<<(WN8 + 255) / 256, 256>>>(Wv, wv, WN8);
    to_half<<<(WN8 + 255) / 256, 256>>>(Wo, wo, WN8);

    dim3 ggrid(E / BN, M_ROWS / BM);      // (8, 64)
    f16_gemm<<<ggrid, 256, GEMM_SMEM>>>(xh, wq, bq, q, 1, 0.125f);  // Q: rope + 1/sqrt(d)
    f16_gemm<<<ggrid, 256, GEMM_SMEM>>>(xh, wk, bk, k, 1, 1.0f);    // K: rope
    f16_gemm<<<ggrid, 256, GEMM_SMEM>>>(xh, wv, bv, v, 2, 1.0f);    // V: scatter

    attn_mma<<<dim3(S / 128, B * H), 128>>>();

    f16_gemm<<<ggrid, 256, GEMM_SMEM>>>(ctx, wo, bo, out, 0, 1.0f); // O projection
}